// round 3
// baseline (speedup 1.0000x reference)
#include <cuda_runtime.h>
#include <cuda_bf16.h>
#include <cstdint>

// Problem constants (match reference)
#define NTOK 16384
#define DIM  768
#define HID  768
#define COUT 2
#define NEXP 20

// GEMM1 tiling
#define BM 128
#define BN 128
#define BK 16

typedef unsigned long long ull;

// packed f32x2 FMA: d = a*b + d (lanewise on two fp32)
#define FMA2(d, a, b) asm("fma.rn.f32x2 %0, %1, %2, %0;" : "+l"(d) : "l"(a), "l"(b))

// -------- device scratch (no allocations allowed) --------
__device__ int   g_offsets[NEXP + 1];
__device__ int   g_sorted_idx[NTOK];     // original token id at sorted position
__device__ int   g_sorted_expert[NTOK];  // expert id at sorted position
__device__ float g_h[(size_t)NTOK * HID]; // hidden activations, sorted layout (~50MB)

// -------- kernel 1: fused prologue (dtype detect + hist + scan + scatter) --------
// Single block, 256 threads. component_idx may be int32 or int64 depending on
// the generator's x64 mode; detect by checking odd int32 words (zero for int64
// little-endian values in [0,20), random expert ids for int32).
__global__ __launch_bounds__(256) void k_prep(const int* __restrict__ idx32) {
    __shared__ int s_cnt[NEXP];
    __shared__ int s_off[NEXP + 1];
    __shared__ int s_is64;
    const int t = threadIdx.x;

    if (t < NEXP) s_cnt[t] = 0;
    if (t == 0) s_is64 = 1;
    __syncthreads();

    for (int i = t; i < NTOK; i += 256)
        if ((i & 1) && idx32[i] != 0) s_is64 = 0;
    __syncthreads();
    const int is64 = s_is64;

    // histogram
    for (int n = t; n < NTOK; n += 256) {
        int e = is64 ? (int)((const long long*)idx32)[n] : idx32[n];
        atomicAdd(&s_cnt[e], 1);
    }
    __syncthreads();

    // exclusive scan (E=20)
    if (t == 0) {
        int off = 0;
        for (int e = 0; e < NEXP; e++) { s_off[e] = off; off += s_cnt[e]; }
        s_off[NEXP] = off;
    }
    __syncthreads();

    if (t <= NEXP) g_offsets[t] = s_off[t];
    if (t < NEXP)  s_cnt[t] = s_off[t];   // reuse as cursor
    __syncthreads();

    // scatter (order within an expert segment is nondeterministic, but all
    // downstream values are order-independent, so d_out is deterministic)
    for (int n = t; n < NTOK; n += 256) {
        int e = is64 ? (int)((const long long*)idx32)[n] : idx32[n];
        int p = atomicAdd(&s_cnt[e], 1);
        g_sorted_idx[p]    = n;
        g_sorted_expert[p] = e;
    }
}

// -------- kernel 2: grouped GEMM1 + bias + ReLU (FFMA2 inner loop) --------
// h_sorted[s, :] = relu( X[tok(s), :] @ W1[e] + b1[e] )
// grid = (HID/BN, ceil(NTOK/BM), NEXP); blocks beyond an expert's segment exit.
// A is stored DUPLICATED in shared ((a,a) pairs) so the fma.rn.f32x2 inner loop
// needs no pack instructions: acc pairs run along N, B pairs are contiguous.
__global__ __launch_bounds__(256) void k_gemm1(
    const float* __restrict__ X,
    const float* __restrict__ W1,
    const float* __restrict__ b1)
{
    const int e = blockIdx.z;
    const int seg_lo = g_offsets[e];
    const int cnt    = g_offsets[e + 1] - seg_lo;
    const int m0 = blockIdx.y * BM;
    if (m0 >= cnt) return;
    const int n0 = blockIdx.x * BN;
    const int tid = threadIdx.x;

    __shared__ float2 AsDup[BK][BM];   // 16 KB, (a,a) pairs
    __shared__ float  Bs[BK][BN];      // 8 KB

    // A-load mapping: thread loads 8 consecutive K-values of one gathered row
    const int m_a = tid & 127;          // row within M tile
    const int k_a = (tid >> 7) * 8;     // 0 or 8
    const bool row_valid = (m0 + m_a) < cnt;
    const int tok = row_valid ? g_sorted_idx[seg_lo + m0 + m_a] : 0;
    const float* Arow = X + (size_t)tok * DIM;

    // B-load mapping: thread loads float4 along N, two k-planes
    const int n_b = (tid & 31) * 4;     // 0..124
    const int k_b = tid >> 5;           // 0..7
    const float* Bbase = W1 + (size_t)e * DIM * HID + n0;

    const int ty = tid >> 4;   // 0..15  (m micro-tile)
    const int tx = tid & 15;   // 0..15  (n micro-tile)

    ull acc[8][4];             // 8 rows x 4 packed f32x2 (covers 8 n-values)
    #pragma unroll
    for (int i = 0; i < 8; i++)
        #pragma unroll
        for (int j = 0; j < 4; j++) acc[i][j] = 0ull;

    for (int k0 = 0; k0 < DIM; k0 += BK) {
        float4 av0 = *(const float4*)(Arow + k0 + k_a);
        float4 av1 = *(const float4*)(Arow + k0 + k_a + 4);
        float4 bv0 = *(const float4*)(Bbase + (size_t)(k0 + k_b) * HID + n_b);
        float4 bv1 = *(const float4*)(Bbase + (size_t)(k0 + k_b + 8) * HID + n_b);

        __syncthreads();
        AsDup[k_a + 0][m_a] = make_float2(av0.x, av0.x);
        AsDup[k_a + 1][m_a] = make_float2(av0.y, av0.y);
        AsDup[k_a + 2][m_a] = make_float2(av0.z, av0.z);
        AsDup[k_a + 3][m_a] = make_float2(av0.w, av0.w);
        AsDup[k_a + 4][m_a] = make_float2(av1.x, av1.x);
        AsDup[k_a + 5][m_a] = make_float2(av1.y, av1.y);
        AsDup[k_a + 6][m_a] = make_float2(av1.z, av1.z);
        AsDup[k_a + 7][m_a] = make_float2(av1.w, av1.w);
        *(float4*)&Bs[k_b][n_b]     = bv0;
        *(float4*)&Bs[k_b + 8][n_b] = bv1;
        __syncthreads();

        #pragma unroll
        for (int k = 0; k < BK; k++) {
            const ull* ap = (const ull*)&AsDup[k][ty * 8];  // 8 dup pairs
            const ull* bp = (const ull*)&Bs[k][tx * 8];     // 4 contiguous pairs
            ull aa[8], bb[4];
            #pragma unroll
            for (int i = 0; i < 8; i++) aa[i] = ap[i];
            #pragma unroll
            for (int j = 0; j < 4; j++) bb[j] = bp[j];
            #pragma unroll
            for (int i = 0; i < 8; i++)
                #pragma unroll
                for (int j = 0; j < 4; j++)
                    FMA2(acc[i][j], aa[i], bb[j]);
        }
    }

    // epilogue: bias + relu, store to sorted h buffer (vectorized)
    const float* b1e = b1 + e * HID + n0 + tx * 8;
    float bias[8];
    #pragma unroll
    for (int j = 0; j < 8; j++) bias[j] = b1e[j];

    #pragma unroll
    for (int i = 0; i < 8; i++) {
        int m = m0 + ty * 8 + i;
        if (m < cnt) {
            float* hp = g_h + (size_t)(seg_lo + m) * HID + n0 + tx * 8;
            float v[8];
            #pragma unroll
            for (int j = 0; j < 4; j++) {
                unsigned lo = (unsigned)(acc[i][j] & 0xffffffffull);
                unsigned hi = (unsigned)(acc[i][j] >> 32);
                v[2 * j + 0] = __uint_as_float(lo);
                v[2 * j + 1] = __uint_as_float(hi);
            }
            #pragma unroll
            for (int j = 0; j < 8; j++) v[j] = fmaxf(v[j] + bias[j], 0.f);
            *(float4*)(hp)     = make_float4(v[0], v[1], v[2], v[3]);
            *(float4*)(hp + 4) = make_float4(v[4], v[5], v[6], v[7]);
        }
    }
}

// -------- kernel 3: out[tok] = h_sorted[s] @ W2[e] + b2[e], one warp per token --------
__global__ __launch_bounds__(256) void k_gemm2(
    const float* __restrict__ W2,
    const float* __restrict__ b2,
    float* __restrict__ out)
{
    int gwarp = (blockIdx.x * blockDim.x + threadIdx.x) >> 5;
    int lane  = threadIdx.x & 31;
    if (gwarp >= NTOK) return;
    int s   = gwarp;
    int e   = g_sorted_expert[s];
    int tok = g_sorted_idx[s];
    const float* hrow = g_h + (size_t)s * HID;
    const float* w2   = W2 + (size_t)e * HID * COUT;

    float a0 = 0.f, a1 = 0.f;
    #pragma unroll 4
    for (int i = lane; i < HID; i += 32) {
        float hv = hrow[i];
        float2 w = *(const float2*)(w2 + i * 2);
        a0 = fmaf(hv, w.x, a0);
        a1 = fmaf(hv, w.y, a1);
    }
    #pragma unroll
    for (int o = 16; o > 0; o >>= 1) {
        a0 += __shfl_xor_sync(0xFFFFFFFFu, a0, o);
        a1 += __shfl_xor_sync(0xFFFFFFFFu, a1, o);
    }
    if (lane == 0) {
        out[tok * 2 + 0] = a0 + b2[e * 2 + 0];
        out[tok * 2 + 1] = a1 + b2[e * 2 + 1];
    }
}

extern "C" void kernel_launch(void* const* d_in, const int* in_sizes, int n_in,
                              void* d_out, int out_size) {
    const float* X   = (const float*)d_in[0];      // [N, D]
    const void*  cid = d_in[1];                    // [N] int32 or int64
    const float* W1  = (const float*)d_in[2];      // [E, D, H]
    const float* b1  = (const float*)d_in[3];      // [E, H]
    const float* W2  = (const float*)d_in[4];      // [E, H, C]
    const float* b2  = (const float*)d_in[5];      // [E, C]
    float*       out = (float*)d_out;              // [N, C]

    k_prep<<<1, 256>>>((const int*)cid);

    dim3 grid1(HID / BN, (NTOK + BM - 1) / BM, NEXP);
    k_gemm1<<<grid1, 256>>>(X, W1, b1);

    k_gemm2<<<(NTOK * 32 + 255) / 256, 256>>>(W2, b2, out);
}

// round 5
// speedup vs baseline: 2.0525x; 2.0525x over previous
#include <cuda_runtime.h>
#include <cuda_bf16.h>
#include <cstdint>

// Problem constants
#define NTOK 16384
#define DIM  768
#define HID  768
#define COUT 2
#define NEXP 20

// GEMM1 tiling (HMMA warp-level)
#define BM 128
#define BN 128
#define BK 32                  // bf16 K elems per stage
#define NITER (DIM / BK)       // 24
#define SPAD 40                // padded smem row stride in bf16 (80B, 16B-aligned)

// ---------------- device scratch ----------------
__device__ int   g_offsets[NEXP + 1];
__device__ int   g_sorted_idx[NTOK];
__device__ int   g_sorted_expert[NTOK];
__device__ float g_h[(size_t)NTOK * HID];                       // 50 MB
__device__ __nv_bfloat16 g_xh[(size_t)NTOK * DIM];              // hi split of X
__device__ __nv_bfloat16 g_xl[(size_t)NTOK * DIM];              // lo split of X
__device__ __nv_bfloat16 g_w1h[(size_t)NEXP * HID * DIM];       // W1^T hi, [e][n][k]
__device__ __nv_bfloat16 g_w1l[(size_t)NEXP * HID * DIM];       // W1^T lo

__device__ __forceinline__ uint32_t smem_u32(const void* p) {
    uint32_t a;
    asm("{ .reg .u64 t; cvta.to.shared.u64 t, %1; cvt.u32.u64 %0, t; }" : "=r"(a) : "l"(p));
    return a;
}

#define LDMX4(r0, r1, r2, r3, a) \
    asm volatile("ldmatrix.sync.aligned.m8n8.x4.shared.b16 {%0,%1,%2,%3}, [%4];" \
        : "=r"(r0), "=r"(r1), "=r"(r2), "=r"(r3) : "r"(a))

#define MMA16816(d, a, b) \
    asm volatile("mma.sync.aligned.m16n8k16.row.col.f32.bf16.bf16.f32 " \
        "{%0,%1,%2,%3}, {%4,%5,%6,%7}, {%8,%9}, {%0,%1,%2,%3};" \
        : "+f"((d)[0]), "+f"((d)[1]), "+f"((d)[2]), "+f"((d)[3]) \
        : "r"((a)[0]), "r"((a)[1]), "r"((a)[2]), "r"((a)[3]), "r"((b)[0]), "r"((b)[1]))

// -------- kernel 1: fused prologue (detect + hist + scan + scatter) --------
__global__ __launch_bounds__(1024) void k_prep(const int* __restrict__ idx32) {
    __shared__ int s_cnt[NEXP];
    __shared__ int s_off[NEXP + 1];
    __shared__ int s_is64;
    const int t = threadIdx.x, lane = t & 31;

    if (t < NEXP) s_cnt[t] = 0;
    if (t == 0) s_is64 = 1;
    __syncthreads();

    for (int i = t; i < NTOK; i += 1024)
        if ((i & 1) && idx32[i] != 0) s_is64 = 0;
    __syncthreads();
    const int is64 = s_is64;

    for (int n = t; n < NTOK; n += 1024) {
        int e = is64 ? (int)((const long long*)idx32)[n] : idx32[n];
        unsigned m = __match_any_sync(0xFFFFFFFFu, e);
        if (lane == (__ffs(m) - 1)) atomicAdd(&s_cnt[e], __popc(m));
    }
    __syncthreads();

    if (t == 0) {
        int off = 0;
        for (int e = 0; e < NEXP; e++) { s_off[e] = off; off += s_cnt[e]; }
        s_off[NEXP] = off;
    }
    __syncthreads();
    if (t <= NEXP) g_offsets[t] = s_off[t];
    if (t < NEXP)  s_cnt[t] = s_off[t];
    __syncthreads();

    for (int n = t; n < NTOK; n += 1024) {
        int e = is64 ? (int)((const long long*)idx32)[n] : idx32[n];
        unsigned m = __match_any_sync(0xFFFFFFFFu, e);
        int leader = __ffs(m) - 1;
        int rank = __popc(m & ((1u << lane) - 1));
        int base = 0;
        if (lane == leader) base = atomicAdd(&s_cnt[e], __popc(m));
        base = __shfl_sync(0xFFFFFFFFu, base, leader);
        int p = base + rank;
        g_sorted_idx[p] = n;
        g_sorted_expert[p] = e;
    }
}

// -------- kernel 2a: split X into bf16 hi/lo --------
__global__ __launch_bounds__(256) void k_split_x(const float* __restrict__ X) {
    size_t i = ((size_t)blockIdx.x * 256 + threadIdx.x) * 4;
    if (i >= (size_t)NTOK * DIM) return;
    float4 v = *(const float4*)(X + i);
    float f[4] = {v.x, v.y, v.z, v.w};
    unsigned short h[4], l[4];
    #pragma unroll
    for (int j = 0; j < 4; j++) {
        __nv_bfloat16 bh = __float2bfloat16(f[j]);
        __nv_bfloat16 bl = __float2bfloat16(f[j] - __bfloat162float(bh));
        h[j] = __bfloat16_as_ushort(bh);
        l[j] = __bfloat16_as_ushort(bl);
    }
    *(uint2*)(g_xh + i) = make_uint2((unsigned)h[0] | ((unsigned)h[1] << 16),
                                     (unsigned)h[2] | ((unsigned)h[3] << 16));
    *(uint2*)(g_xl + i) = make_uint2((unsigned)l[0] | ((unsigned)l[1] << 16),
                                     (unsigned)l[2] | ((unsigned)l[3] << 16));
}

// -------- kernel 2b: transpose + split W1 -> [e][n][k] bf16 hi/lo --------
__global__ __launch_bounds__(256) void k_split_w1(const float* __restrict__ W1) {
    __shared__ float tile[32][33];
    const int e = blockIdx.z;
    const int kt = blockIdx.y * 32;
    const int nt = blockIdx.x * 32;
    const float* src = W1 + (size_t)e * DIM * HID;

    for (int i = threadIdx.y; i < 32; i += 8)
        tile[i][threadIdx.x] = src[(size_t)(kt + i) * HID + nt + threadIdx.x];
    __syncthreads();

    for (int i = threadIdx.y; i < 32; i += 8) {
        float v = tile[threadIdx.x][i];
        __nv_bfloat16 bh = __float2bfloat16(v);
        __nv_bfloat16 bl = __float2bfloat16(v - __bfloat162float(bh));
        size_t o = ((size_t)e * HID + nt + i) * DIM + kt + threadIdx.x;
        g_w1h[o] = bh;
        g_w1l[o] = bl;
    }
}

// -------- kernel 3: grouped GEMM1 via HMMA (bf16 split) + bias + ReLU --------
// h_sorted[s,:] = relu( X[tok(s),:] @ W1[e] + b1[e] ),
// D = Ah*Bh + Ah*Bl + Al*Bh in fp32 accumulators.
// grid = (HID/BN, NTOK/BM, NEXP), 256 thr = 8 warps (2 along M x 4 along N),
// warp tile 64x32.
__global__ __launch_bounds__(256) void k_gemm1(const float* __restrict__ b1)
{
    __shared__ __align__(16) __nv_bfloat16 sAh[BM * SPAD];
    __shared__ __align__(16) __nv_bfloat16 sAl[BM * SPAD];
    __shared__ __align__(16) __nv_bfloat16 sBh[BN * SPAD];
    __shared__ __align__(16) __nv_bfloat16 sBl[BN * SPAD];

    const int e = blockIdx.z;
    const int seg_lo = g_offsets[e];
    const int cnt    = g_offsets[e + 1] - seg_lo;
    const int m0 = blockIdx.y * BM;
    if (m0 >= cnt) return;
    const int n0 = blockIdx.x * BN;
    const int tid  = threadIdx.x;
    const int wid  = tid >> 5;
    const int lane = tid & 31;

    const int wm = (wid >> 2) * 64;   // warp M offset (0 or 64)
    const int wn = (wid & 3) * 32;    // warp N offset (0,32,64,96)

    // global->smem load mapping: thread handles row (tid&127), half (tid>>7)
    const int r_ld = tid & 127;
    const int h_ld = tid >> 7;                 // 0/1 -> 16-elem half of BK=32
    const int m_ld = m0 + r_ld;
    const int tok  = (m_ld < cnt) ? g_sorted_idx[seg_lo + m_ld] : g_sorted_idx[seg_lo];
    const __nv_bfloat16* pAh = g_xh + (size_t)tok * DIM + h_ld * 16;
    const __nv_bfloat16* pAl = g_xl + (size_t)tok * DIM + h_ld * 16;
    const __nv_bfloat16* pBh = g_w1h + ((size_t)e * HID + n0 + r_ld) * DIM + h_ld * 16;
    const __nv_bfloat16* pBl = g_w1l + ((size_t)e * HID + n0 + r_ld) * DIM + h_ld * 16;
    const int s_off16 = r_ld * SPAD + h_ld * 16;   // in bf16 elems

    // ldmatrix base addresses (byte offsets within padded tiles)
    const uint32_t aAh = smem_u32(sAh), aAl = smem_u32(sAl);
    const uint32_t aBh = smem_u32(sBh), aBl = smem_u32(sBl);
    // A: row = wm + mt*16 + (lane&15), kbyte = ks*32 + (lane>>4)*16
    const int a_row = wm + (lane & 15);
    const int a_kb  = (lane >> 4) * 16;
    // B: n = wn + p*16 + ((lane>>4)&1)*8 + (lane&7), kbyte = ks*32 + ((lane>>3)&1)*16
    const int b_row = wn + ((lane >> 4) & 1) * 8 + (lane & 7);
    const int b_kb  = ((lane >> 3) & 1) * 16;

    float acc[4][4][4];   // [mtile][ntile][frag]
    #pragma unroll
    for (int i = 0; i < 4; i++)
        #pragma unroll
        for (int j = 0; j < 4; j++)
            #pragma unroll
            for (int q = 0; q < 4; q++) acc[i][j][q] = 0.f;

    for (int c = 0; c < NITER; c++) {
        const int kg = c * BK;
        uint4 vah = *(const uint4*)(pAh + kg);
        uint4 val_ = *(const uint4*)(pAl + kg);
        uint4 vbh = *(const uint4*)(pBh + kg);
        uint4 vbl = *(const uint4*)(pBl + kg);
        uint4 vah2 = *(const uint4*)(pAh + kg + 8);
        uint4 val2 = *(const uint4*)(pAl + kg + 8);
        uint4 vbh2 = *(const uint4*)(pBh + kg + 8);
        uint4 vbl2 = *(const uint4*)(pBl + kg + 8);

        __syncthreads();
        *(uint4*)(sAh + s_off16)     = vah;
        *(uint4*)(sAh + s_off16 + 8) = vah2;
        *(uint4*)(sAl + s_off16)     = val_;
        *(uint4*)(sAl + s_off16 + 8) = val2;
        *(uint4*)(sBh + s_off16)     = vbh;
        *(uint4*)(sBh + s_off16 + 8) = vbh2;
        *(uint4*)(sBl + s_off16)     = vbl;
        *(uint4*)(sBl + s_off16 + 8) = vbl2;
        __syncthreads();

        #pragma unroll
        for (int ks = 0; ks < 2; ks++) {
            uint32_t fah[4][4], fal[4][4], fbh[4][2], fbl[4][2];
            #pragma unroll
            for (int mt = 0; mt < 4; mt++) {
                uint32_t oa = (uint32_t)((a_row + mt * 16) * (SPAD * 2) + ks * 32 + a_kb);
                LDMX4(fah[mt][0], fah[mt][1], fah[mt][2], fah[mt][3], aAh + oa);
                LDMX4(fal[mt][0], fal[mt][1], fal[mt][2], fal[mt][3], aAl + oa);
            }
            #pragma unroll
            for (int p = 0; p < 2; p++) {
                uint32_t ob = (uint32_t)((b_row + p * 16) * (SPAD * 2) + ks * 32 + b_kb);
                LDMX4(fbh[2 * p][0], fbh[2 * p][1], fbh[2 * p + 1][0], fbh[2 * p + 1][1], aBh + ob);
                LDMX4(fbl[2 * p][0], fbl[2 * p][1], fbl[2 * p + 1][0], fbl[2 * p + 1][1], aBl + ob);
            }
            #pragma unroll
            for (int mt = 0; mt < 4; mt++)
                #pragma unroll
                for (int nt = 0; nt < 4; nt++) {
                    MMA16816(acc[mt][nt], fah[mt], fbh[nt]);
                    MMA16816(acc[mt][nt], fah[mt], fbl[nt]);
                    MMA16816(acc[mt][nt], fal[mt], fbh[nt]);
                }
        }
    }

    // epilogue: bias + ReLU, direct fragment stores to g_h (sorted layout)
    #pragma unroll
    for (int nt = 0; nt < 4; nt++) {
        const int ncol = n0 + wn + nt * 8 + (lane & 3) * 2;
        const float bia0 = b1[e * HID + ncol];
        const float bia1 = b1[e * HID + ncol + 1];
        #pragma unroll
        for (int mt = 0; mt < 4; mt++) {
            int r0 = wm + mt * 16 + (lane >> 2);
            int ma = m0 + r0;
            if (ma < cnt) {
                float2 v;
                v.x = fmaxf(acc[mt][nt][0] + bia0, 0.f);
                v.y = fmaxf(acc[mt][nt][1] + bia1, 0.f);
                *(float2*)(g_h + (size_t)(seg_lo + ma) * HID + ncol) = v;
            }
            int mb = ma + 8;
            if (mb < cnt) {
                float2 v;
                v.x = fmaxf(acc[mt][nt][2] + bia0, 0.f);
                v.y = fmaxf(acc[mt][nt][3] + bia1, 0.f);
                *(float2*)(g_h + (size_t)(seg_lo + mb) * HID + ncol) = v;
            }
        }
    }
}

// -------- kernel 4: out[tok] = h_sorted[s] @ W2[e] + b2[e], one warp per token --------
__global__ __launch_bounds__(256) void k_gemm2(
    const float* __restrict__ W2,
    const float* __restrict__ b2,
    float* __restrict__ out)
{
    int gwarp = (blockIdx.x * blockDim.x + threadIdx.x) >> 5;
    int lane  = threadIdx.x & 31;
    if (gwarp >= NTOK) return;
    int s   = gwarp;
    int e   = g_sorted_expert[s];
    int tok = g_sorted_idx[s];
    const float* hrow = g_h + (size_t)s * HID;
    const float* w2   = W2 + (size_t)e * HID * COUT;

    float a0 = 0.f, a1 = 0.f;
    #pragma unroll 4
    for (int i = lane; i < HID; i += 32) {
        float hv = hrow[i];
        float2 w = *(const float2*)(w2 + i * 2);
        a0 = fmaf(hv, w.x, a0);
        a1 = fmaf(hv, w.y, a1);
    }
    #pragma unroll
    for (int o = 16; o > 0; o >>= 1) {
        a0 += __shfl_xor_sync(0xFFFFFFFFu, a0, o);
        a1 += __shfl_xor_sync(0xFFFFFFFFu, a1, o);
    }
    if (lane == 0) {
        out[tok * 2 + 0] = a0 + b2[e * 2 + 0];
        out[tok * 2 + 1] = a1 + b2[e * 2 + 1];
    }
}

extern "C" void kernel_launch(void* const* d_in, const int* in_sizes, int n_in,
                              void* d_out, int out_size) {
    const float* X   = (const float*)d_in[0];      // [N, D]
    const void*  cid = d_in[1];                    // [N] int32 or int64
    const float* W1  = (const float*)d_in[2];      // [E, D, H]
    const float* b1  = (const float*)d_in[3];      // [E, H]
    const float* W2  = (const float*)d_in[4];      // [E, H, C]
    const float* b2  = (const float*)d_in[5];      // [E, C]
    float*       out = (float*)d_out;              // [N, C]

    k_prep<<<1, 1024>>>((const int*)cid);
    k_split_x<<<(int)(((size_t)NTOK * DIM / 4 + 255) / 256), 256>>>(X);
    k_split_w1<<<dim3(HID / 32, DIM / 32, NEXP), dim3(32, 8)>>>(W1);

    dim3 grid1(HID / BN, NTOK / BM, NEXP);
    k_gemm1<<<grid1, 256>>>(b1);

    k_gemm2<<<(NTOK * 32 + 255) / 256, 256>>>(W2, b2, out);
}

// round 7
// speedup vs baseline: 2.4208x; 1.1794x over previous
#include <cuda_runtime.h>
#include <cuda_fp16.h>
#include <cuda_bf16.h>
#include <cstdint>

// Problem constants
#define NTOK 16384
#define DIM  768
#define HID  768
#define COUT 2
#define NEXP 20

// GEMM1 tiling (HMMA warp-level)
#define BM 128
#define BN 256
#define BK 32                  // fp16 K elems per stage
#define NITER (DIM / BK)       // 24
#define SPAD 40                // padded smem row stride in fp16 (80B)

// ---------------- device scratch ----------------
__device__ int    g_offsets[NEXP + 1];
__device__ int    g_sorted_idx[NTOK];
__device__ int    g_sorted_expert[NTOK];
__device__ float  g_h[(size_t)NTOK * HID];                 // 50 MB
__device__ __half g_xh[(size_t)NTOK * DIM];                // hi split of X (fp16)
__device__ __half g_xl[(size_t)NTOK * DIM];                // lo split of X (fp16)
__device__ __half g_w1f[(size_t)NEXP * HID * DIM];         // W1^T fp16, [e][n][k]

__device__ __forceinline__ uint32_t smem_u32(const void* p) {
    uint32_t a;
    asm("{ .reg .u64 t; cvta.to.shared.u64 t, %1; cvt.u32.u64 %0, t; }" : "=r"(a) : "l"(p));
    return a;
}

#define LDMX4(r0, r1, r2, r3, a) \
    asm volatile("ldmatrix.sync.aligned.m8n8.x4.shared.b16 {%0,%1,%2,%3}, [%4];" \
        : "=r"(r0), "=r"(r1), "=r"(r2), "=r"(r3) : "r"(a))

#define MMAF16(d, a, b) \
    asm volatile("mma.sync.aligned.m16n8k16.row.col.f32.f16.f16.f32 " \
        "{%0,%1,%2,%3}, {%4,%5,%6,%7}, {%8,%9}, {%0,%1,%2,%3};" \
        : "+f"((d)[0]), "+f"((d)[1]), "+f"((d)[2]), "+f"((d)[3]) \
        : "r"((a)[0]), "r"((a)[1]), "r"((a)[2]), "r"((a)[3]), "r"((b)[0]), "r"((b)[1]))

// -------- kernel 1: fused prologue (detect + hist + scan + scatter) --------
__global__ __launch_bounds__(1024) void k_prep(const int* __restrict__ idx32) {
    __shared__ int s_cnt[NEXP];
    __shared__ int s_off[NEXP + 1];
    __shared__ int s_is64;
    const int t = threadIdx.x, lane = t & 31;

    if (t < NEXP) s_cnt[t] = 0;
    if (t == 0) s_is64 = 1;
    __syncthreads();

    for (int i = t; i < NTOK; i += 1024)
        if ((i & 1) && idx32[i] != 0) s_is64 = 0;
    __syncthreads();
    const int is64 = s_is64;

    for (int n = t; n < NTOK; n += 1024) {
        int e = is64 ? (int)((const long long*)idx32)[n] : idx32[n];
        unsigned m = __match_any_sync(0xFFFFFFFFu, e);
        if (lane == (__ffs(m) - 1)) atomicAdd(&s_cnt[e], __popc(m));
    }
    __syncthreads();

    if (t == 0) {
        int off = 0;
        for (int e = 0; e < NEXP; e++) { s_off[e] = off; off += s_cnt[e]; }
        s_off[NEXP] = off;
    }
    __syncthreads();
    if (t <= NEXP) g_offsets[t] = s_off[t];
    if (t < NEXP)  s_cnt[t] = s_off[t];
    __syncthreads();

    for (int n = t; n < NTOK; n += 1024) {
        int e = is64 ? (int)((const long long*)idx32)[n] : idx32[n];
        unsigned m = __match_any_sync(0xFFFFFFFFu, e);
        int leader = __ffs(m) - 1;
        int rank = __popc(m & ((1u << lane) - 1));
        int base = 0;
        if (lane == leader) base = atomicAdd(&s_cnt[e], __popc(m));
        base = __shfl_sync(0xFFFFFFFFu, base, leader);
        int p = base + rank;
        g_sorted_idx[p] = n;
        g_sorted_expert[p] = e;
    }
}

// -------- kernel 2a: split X into fp16 hi/lo --------
__global__ __launch_bounds__(256) void k_split_x(const float* __restrict__ X) {
    size_t i = ((size_t)blockIdx.x * 256 + threadIdx.x) * 4;
    if (i >= (size_t)NTOK * DIM) return;
    float4 v = *(const float4*)(X + i);
    float f[4] = {v.x, v.y, v.z, v.w};
    unsigned short h[4], l[4];
    #pragma unroll
    for (int j = 0; j < 4; j++) {
        __half hh = __float2half_rn(f[j]);
        __half hl = __float2half_rn(f[j] - __half2float(hh));
        h[j] = __half_as_ushort(hh);
        l[j] = __half_as_ushort(hl);
    }
    *(uint2*)(g_xh + i) = make_uint2((unsigned)h[0] | ((unsigned)h[1] << 16),
                                     (unsigned)h[2] | ((unsigned)h[3] << 16));
    *(uint2*)(g_xl + i) = make_uint2((unsigned)l[0] | ((unsigned)l[1] << 16),
                                     (unsigned)l[2] | ((unsigned)l[3] << 16));
}

// -------- kernel 2b: transpose W1 -> [e][n][k] fp16 --------
__global__ __launch_bounds__(256) void k_split_w1(const float* __restrict__ W1) {
    __shared__ float tile[32][33];
    const int e = blockIdx.z;
    const int kt = blockIdx.y * 32;
    const int nt = blockIdx.x * 32;
    const float* src = W1 + (size_t)e * DIM * HID;

    for (int i = threadIdx.y; i < 32; i += 8)
        tile[i][threadIdx.x] = src[(size_t)(kt + i) * HID + nt + threadIdx.x];
    __syncthreads();

    for (int i = threadIdx.y; i < 32; i += 8) {
        float v = tile[threadIdx.x][i];
        size_t o = ((size_t)e * HID + nt + i) * DIM + kt + threadIdx.x;
        g_w1f[o] = __float2half_rn(v);
    }
}

// -------- kernel 3: grouped GEMM1 via fp16 HMMA (2-product X-split) + bias + ReLU --------
// h_sorted[s,:] = relu( X[tok(s),:] @ W1[e] + b1[e] ),  D = Xh*W + Xl*W in fp32.
// grid = (HID/BN=3, NTOK/BM, NEXP), 256 thr = 8 warps (2 along M x 4 along N),
// warp tile 64x64.
__global__ __launch_bounds__(256, 1) void k_gemm1(const float* __restrict__ b1)
{
    __shared__ __align__(16) __half sXh[BM * SPAD];   // 10 KB
    __shared__ __align__(16) __half sXl[BM * SPAD];   // 10 KB
    __shared__ __align__(16) __half sW [BN * SPAD];   // 20 KB

    const int e = blockIdx.z;
    const int seg_lo = g_offsets[e];
    const int cnt    = g_offsets[e + 1] - seg_lo;
    const int m0 = blockIdx.y * BM;
    if (m0 >= cnt) return;
    const int n0 = blockIdx.x * BN;
    const int tid  = threadIdx.x;
    const int wid  = tid >> 5;
    const int lane = tid & 31;

    const int wm = (wid >> 2) * 64;   // warp M offset (0 or 64)
    const int wn = (wid & 3) * 64;    // warp N offset (0,64,128,192)

    // global->smem mapping:
    //  A: thread (r = tid&127, half = tid>>7) loads 16 fp16 (32B) of Xh and Xl
    //  W: thread tid loads full 32-elem k-row (64B)
    const int r_ld = tid & 127;
    const int h_ld = (tid >> 7) * 16;
    const int m_ld = m0 + r_ld;
    const int tok  = (m_ld < cnt) ? g_sorted_idx[seg_lo + m_ld] : g_sorted_idx[seg_lo];
    const __half* pXh = g_xh + (size_t)tok * DIM + h_ld;
    const __half* pXl = g_xl + (size_t)tok * DIM + h_ld;
    const __half* pW  = g_w1f + ((size_t)e * HID + n0 + tid) * DIM;
    const int sA_off = r_ld * SPAD + h_ld;
    const int sW_off = tid * SPAD;

    const uint32_t aXh = smem_u32(sXh), aXl = smem_u32(sXl), aW = smem_u32(sW);
    // ldmatrix lane addressing (byte offsets; row stride 80B)
    const int a_row = wm + (lane & 15);
    const int a_kb  = (lane >> 4) * 16;
    const int b_row = wn + ((lane >> 4) & 1) * 8 + (lane & 7);
    const int b_kb  = ((lane >> 3) & 1) * 16;

    float acc[4][8][4];
    #pragma unroll
    for (int i = 0; i < 4; i++)
        #pragma unroll
        for (int j = 0; j < 8; j++)
            #pragma unroll
            for (int q = 0; q < 4; q++) acc[i][j][q] = 0.f;

    for (int c = 0; c < NITER; c++) {
        const int kg = c * BK;
        uint4 vxh0 = *(const uint4*)(pXh + kg);
        uint4 vxh1 = *(const uint4*)(pXh + kg + 8);
        uint4 vxl0 = *(const uint4*)(pXl + kg);
        uint4 vxl1 = *(const uint4*)(pXl + kg + 8);
        uint4 vw0  = *(const uint4*)(pW + kg);
        uint4 vw1  = *(const uint4*)(pW + kg + 8);
        uint4 vw2  = *(const uint4*)(pW + kg + 16);
        uint4 vw3  = *(const uint4*)(pW + kg + 24);

        __syncthreads();
        *(uint4*)(sXh + sA_off)     = vxh0;
        *(uint4*)(sXh + sA_off + 8) = vxh1;
        *(uint4*)(sXl + sA_off)     = vxl0;
        *(uint4*)(sXl + sA_off + 8) = vxl1;
        *(uint4*)(sW + sW_off)      = vw0;
        *(uint4*)(sW + sW_off + 8)  = vw1;
        *(uint4*)(sW + sW_off + 16) = vw2;
        *(uint4*)(sW + sW_off + 24) = vw3;
        __syncthreads();

        #pragma unroll
        for (int ks = 0; ks < 2; ks++) {
            uint32_t fxh[4][4], fxl[4][4], fw[8][2];
            #pragma unroll
            for (int mt = 0; mt < 4; mt++) {
                uint32_t oa = (uint32_t)((a_row + mt * 16) * (SPAD * 2) + ks * 32 + a_kb);
                LDMX4(fxh[mt][0], fxh[mt][1], fxh[mt][2], fxh[mt][3], aXh + oa);
                LDMX4(fxl[mt][0], fxl[mt][1], fxl[mt][2], fxl[mt][3], aXl + oa);
            }
            #pragma unroll
            for (int p = 0; p < 4; p++) {
                uint32_t ob = (uint32_t)((b_row + p * 16) * (SPAD * 2) + ks * 32 + b_kb);
                LDMX4(fw[2 * p][0], fw[2 * p][1], fw[2 * p + 1][0], fw[2 * p + 1][1], aW + ob);
            }
            #pragma unroll
            for (int mt = 0; mt < 4; mt++)
                #pragma unroll
                for (int nt = 0; nt < 8; nt++) {
                    MMAF16(acc[mt][nt], fxh[mt], fw[nt]);
                    MMAF16(acc[mt][nt], fxl[mt], fw[nt]);
                }
        }
    }

    // epilogue: bias + ReLU, fragment stores to g_h (sorted layout)
    #pragma unroll
    for (int nt = 0; nt < 8; nt++) {
        const int ncol = n0 + wn + nt * 8 + (lane & 3) * 2;
        const float bia0 = b1[e * HID + ncol];
        const float bia1 = b1[e * HID + ncol + 1];
        #pragma unroll
        for (int mt = 0; mt < 4; mt++) {
            int r0 = wm + mt * 16 + (lane >> 2);
            int ma = m0 + r0;
            if (ma < cnt) {
                float2 v;
                v.x = fmaxf(acc[mt][nt][0] + bia0, 0.f);
                v.y = fmaxf(acc[mt][nt][1] + bia1, 0.f);
                *(float2*)(g_h + (size_t)(seg_lo + ma) * HID + ncol) = v;
            }
            int mb = ma + 8;
            if (mb < cnt) {
                float2 v;
                v.x = fmaxf(acc[mt][nt][2] + bia0, 0.f);
                v.y = fmaxf(acc[mt][nt][3] + bia1, 0.f);
                *(float2*)(g_h + (size_t)(seg_lo + mb) * HID + ncol) = v;
            }
        }
    }
}

// -------- kernel 4: out[tok] = h_sorted[s] @ W2[e] + b2[e], one warp per token --------
__global__ __launch_bounds__(256) void k_gemm2(
    const float* __restrict__ W2,
    const float* __restrict__ b2,
    float* __restrict__ out)
{
    int gwarp = (blockIdx.x * blockDim.x + threadIdx.x) >> 5;
    int lane  = threadIdx.x & 31;
    if (gwarp >= NTOK) return;
    int s   = gwarp;
    int e   = g_sorted_expert[s];
    int tok = g_sorted_idx[s];
    const float* hrow = g_h + (size_t)s * HID;
    const float* w2   = W2 + (size_t)e * HID * COUT;

    float a0 = 0.f, a1 = 0.f;
    #pragma unroll 4
    for (int i = lane; i < HID; i += 32) {
        float hv = hrow[i];
        float2 w = *(const float2*)(w2 + i * 2);
        a0 = fmaf(hv, w.x, a0);
        a1 = fmaf(hv, w.y, a1);
    }
    #pragma unroll
    for (int o = 16; o > 0; o >>= 1) {
        a0 += __shfl_xor_sync(0xFFFFFFFFu, a0, o);
        a1 += __shfl_xor_sync(0xFFFFFFFFu, a1, o);
    }
    if (lane == 0) {
        out[tok * 2 + 0] = a0 + b2[e * 2 + 0];
        out[tok * 2 + 1] = a1 + b2[e * 2 + 1];
    }
}

extern "C" void kernel_launch(void* const* d_in, const int* in_sizes, int n_in,
                              void* d_out, int out_size) {
    const float* X   = (const float*)d_in[0];      // [N, D]
    const void*  cid = d_in[1];                    // [N] int32 or int64
    const float* W1  = (const float*)d_in[2];      // [E, D, H]
    const float* b1  = (const float*)d_in[3];      // [E, H]
    const float* W2  = (const float*)d_in[4];      // [E, H, C]
    const float* b2  = (const float*)d_in[5];      // [E, C]
    float*       out = (float*)d_out;              // [N, C]

    k_prep<<<1, 1024>>>((const int*)cid);
    k_split_x<<<(int)(((size_t)NTOK * DIM / 4 + 255) / 256), 256>>>(X);
    k_split_w1<<<dim3(HID / 32, DIM / 32, NEXP), dim3(32, 8)>>>(W1);

    dim3 grid1(HID / BN, NTOK / BM, NEXP);
    k_gemm1<<<grid1, 256>>>(b1);

    k_gemm2<<<(NTOK * 32 + 255) / 256, 256>>>(W2, b2, out);
}

// round 9
// speedup vs baseline: 2.6372x; 1.0894x over previous
#include <cuda_runtime.h>
#include <cuda_fp16.h>
#include <cuda_bf16.h>
#include <cstdint>

// Problem constants
#define NTOK 16384
#define DIM  768
#define HID  768
#define COUT 2
#define NEXP 20

// GEMM1 tiling (HMMA warp-level, cp.async 3-stage pipeline)
#define BM 128
#define BN 256
#define BK 32                  // fp16 K elems per stage
#define NITER (DIM / BK)       // 24
#define SPAD 40                // padded smem row stride in fp16 (80B)
#define NSTAGE 3
#define ST_XH 0
#define ST_XL (BM * SPAD)                  // halfs
#define ST_W  (2 * BM * SPAD)
#define STAGE_HALFS (2 * BM * SPAD + BN * SPAD)   // 20480
#define STAGE_BYTES (STAGE_HALFS * 2)             // 40960
#define SMEM_TOTAL (NSTAGE * STAGE_BYTES)         // 122880

// ---------------- device scratch ----------------
__device__ int    g_offsets[NEXP + 1];
__device__ int    g_sorted_idx[NTOK];
__device__ int    g_sorted_expert[NTOK];
__device__ float  g_h[(size_t)NTOK * HID];                 // 50 MB
__device__ __half g_xh[(size_t)NTOK * DIM];                // hi split of X (fp16)
__device__ __half g_xl[(size_t)NTOK * DIM];                // lo split of X (fp16)
__device__ __half g_w1f[(size_t)NEXP * HID * DIM];         // W1^T fp16, [e][n][k]

__device__ __forceinline__ uint32_t smem_u32(const void* p) {
    uint32_t a;
    asm("{ .reg .u64 t; cvta.to.shared.u64 t, %1; cvt.u32.u64 %0, t; }" : "=r"(a) : "l"(p));
    return a;
}

#define CP16(dst, src) \
    asm volatile("cp.async.cg.shared.global [%0], [%1], 16;" :: "r"(dst), "l"(src))
#define CP_COMMIT() asm volatile("cp.async.commit_group;")

#define LDMX4(r0, r1, r2, r3, a) \
    asm volatile("ldmatrix.sync.aligned.m8n8.x4.shared.b16 {%0,%1,%2,%3}, [%4];" \
        : "=r"(r0), "=r"(r1), "=r"(r2), "=r"(r3) : "r"(a))

#define MMAF16(d, a, b) \
    asm volatile("mma.sync.aligned.m16n8k16.row.col.f32.f16.f16.f32 " \
        "{%0,%1,%2,%3}, {%4,%5,%6,%7}, {%8,%9}, {%0,%1,%2,%3};" \
        : "+f"((d)[0]), "+f"((d)[1]), "+f"((d)[2]), "+f"((d)[3]) \
        : "r"((a)[0]), "r"((a)[1]), "r"((a)[2]), "r"((a)[3]), "r"((b)[0]), "r"((b)[1]))

// -------- kernel 1: fused prologue (detect + hist + scan + scatter) --------
__global__ __launch_bounds__(1024) void k_prep(const int* __restrict__ idx32) {
    __shared__ int s_cnt[NEXP];
    __shared__ int s_off[NEXP + 1];
    __shared__ int s_is64;
    const int t = threadIdx.x, lane = t & 31;

    if (t < NEXP) s_cnt[t] = 0;
    if (t == 0) s_is64 = 1;
    __syncthreads();

    for (int i = t; i < NTOK; i += 1024)
        if ((i & 1) && idx32[i] != 0) s_is64 = 0;
    __syncthreads();
    const int is64 = s_is64;

    for (int n = t; n < NTOK; n += 1024) {
        int e = is64 ? (int)((const long long*)idx32)[n] : idx32[n];
        unsigned m = __match_any_sync(0xFFFFFFFFu, e);
        if (lane == (__ffs(m) - 1)) atomicAdd(&s_cnt[e], __popc(m));
    }
    __syncthreads();

    if (t == 0) {
        int off = 0;
        for (int e = 0; e < NEXP; e++) { s_off[e] = off; off += s_cnt[e]; }
        s_off[NEXP] = off;
    }
    __syncthreads();
    if (t <= NEXP) g_offsets[t] = s_off[t];
    if (t < NEXP)  s_cnt[t] = s_off[t];
    __syncthreads();

    for (int n = t; n < NTOK; n += 1024) {
        int e = is64 ? (int)((const long long*)idx32)[n] : idx32[n];
        unsigned m = __match_any_sync(0xFFFFFFFFu, e);
        int leader = __ffs(m) - 1;
        int rank = __popc(m & ((1u << lane) - 1));
        int base = 0;
        if (lane == leader) base = atomicAdd(&s_cnt[e], __popc(m));
        base = __shfl_sync(0xFFFFFFFFu, base, leader);
        int p = base + rank;
        g_sorted_idx[p] = n;
        g_sorted_expert[p] = e;
    }
}

// -------- kernel 2a: split X into fp16 hi/lo --------
__global__ __launch_bounds__(256) void k_split_x(const float* __restrict__ X) {
    size_t i = ((size_t)blockIdx.x * 256 + threadIdx.x) * 4;
    if (i >= (size_t)NTOK * DIM) return;
    float4 v = *(const float4*)(X + i);
    float f[4] = {v.x, v.y, v.z, v.w};
    unsigned short h[4], l[4];
    #pragma unroll
    for (int j = 0; j < 4; j++) {
        __half hh = __float2half_rn(f[j]);
        __half hl = __float2half_rn(f[j] - __half2float(hh));
        h[j] = __half_as_ushort(hh);
        l[j] = __half_as_ushort(hl);
    }
    *(uint2*)(g_xh + i) = make_uint2((unsigned)h[0] | ((unsigned)h[1] << 16),
                                     (unsigned)h[2] | ((unsigned)h[3] << 16));
    *(uint2*)(g_xl + i) = make_uint2((unsigned)l[0] | ((unsigned)l[1] << 16),
                                     (unsigned)l[2] | ((unsigned)l[3] << 16));
}

// -------- kernel 2b: transpose W1 -> [e][n][k] fp16 --------
__global__ __launch_bounds__(256) void k_split_w1(const float* __restrict__ W1) {
    __shared__ float tile[32][33];
    const int e = blockIdx.z;
    const int kt = blockIdx.y * 32;
    const int nt = blockIdx.x * 32;
    const float* src = W1 + (size_t)e * DIM * HID;

    for (int i = threadIdx.y; i < 32; i += 8)
        tile[i][threadIdx.x] = src[(size_t)(kt + i) * HID + nt + threadIdx.x];
    __syncthreads();

    for (int i = threadIdx.y; i < 32; i += 8) {
        float v = tile[threadIdx.x][i];
        size_t o = ((size_t)e * HID + nt + i) * DIM + kt + threadIdx.x;
        g_w1f[o] = __float2half_rn(v);
    }
}

// -------- kernel 3: grouped GEMM1, fp16 HMMA + cp.async 3-stage pipeline --------
// h_sorted[s,:] = relu( X[tok(s),:] @ W1[e] + b1[e] ),  D = Xh*W + Xl*W in fp32.
// grid = (HID/BN=3, NTOK/BM, NEXP), 256 thr = 8 warps (2 M x 4 N), warp tile 64x64.
__global__ __launch_bounds__(256, 1) void k_gemm1(const float* __restrict__ b1)
{
    extern __shared__ __align__(16) __half dynsm[];
    const uint32_t smem0 = smem_u32(dynsm);

    const int e = blockIdx.z;
    const int seg_lo = g_offsets[e];
    const int cnt    = g_offsets[e + 1] - seg_lo;
    const int m0 = blockIdx.y * BM;
    if (m0 >= cnt) return;
    const int n0 = blockIdx.x * BN;
    const int tid  = threadIdx.x;
    const int wid  = tid >> 5;
    const int lane = tid & 31;

    const int wm = (wid >> 2) * 64;   // warp M offset (0 or 64)
    const int wn = (wid & 3) * 64;    // warp N offset (0,64,128,192)

    // global source pointers for this thread's slice of each stage
    const int r_ld = tid & 127;
    const int h_ld = (tid >> 7) * 16;
    const int m_ld = m0 + r_ld;
    const int tok  = (m_ld < cnt) ? g_sorted_idx[seg_lo + m_ld] : g_sorted_idx[seg_lo];
    const __half* pXh = g_xh + (size_t)tok * DIM + h_ld;
    const __half* pXl = g_xl + (size_t)tok * DIM + h_ld;
    const __half* pW  = g_w1f + ((size_t)e * HID + n0 + tid) * DIM;
    const uint32_t dA_off = (uint32_t)(r_ld * SPAD + h_ld) * 2;   // bytes
    const uint32_t dW_off = (uint32_t)(tid * SPAD) * 2;

    // ldmatrix lane addressing (byte offsets within a stage; row stride 80B)
    const int a_row = wm + (lane & 15);
    const int a_kb  = (lane >> 4) * 16;
    const int b_row = wn + ((lane >> 4) & 1) * 8 + (lane & 7);
    const int b_kb  = ((lane >> 3) & 1) * 16;

    float acc[4][8][4];
    #pragma unroll
    for (int i = 0; i < 4; i++)
        #pragma unroll
        for (int j = 0; j < 8; j++)
            #pragma unroll
            for (int q = 0; q < 4; q++) acc[i][j][q] = 0.f;

    // issue one stage's cp.async (8 x 16B per thread)
    auto issue = [&](int c, int st) {
        const int kg = c * BK;
        const uint32_t sb = smem0 + st * STAGE_BYTES;
        uint32_t dXh = sb + dA_off;
        uint32_t dXl = sb + ST_XL * 2 + dA_off;
        uint32_t dW  = sb + ST_W * 2 + dW_off;
        CP16(dXh,      pXh + kg);
        CP16(dXh + 16, pXh + kg + 8);
        CP16(dXl,      pXl + kg);
        CP16(dXl + 16, pXl + kg + 8);
        CP16(dW,       pW + kg);
        CP16(dW + 16,  pW + kg + 8);
        CP16(dW + 32,  pW + kg + 16);
        CP16(dW + 48,  pW + kg + 24);
        CP_COMMIT();
    };

    issue(0, 0);
    issue(1, 1);

    int st = 0;
    for (int c = 0; c < NITER; c++) {
        // stage c must be complete (at most 1 newer group may stay pending)
        if (c + 1 < NITER) { asm volatile("cp.async.wait_group 1;" ::: "memory"); }
        else               { asm volatile("cp.async.wait_group 0;" ::: "memory"); }
        __syncthreads();

        // refill the oldest-free buffer (was read at iter c-1; sync above protects it)
        if (c + 2 < NITER) {
            int st2 = st + 2; if (st2 >= NSTAGE) st2 -= NSTAGE;
            issue(c + 2, st2);
        }

        const uint32_t sb  = smem0 + st * STAGE_BYTES;
        const uint32_t bXh = sb;
        const uint32_t bXl = sb + ST_XL * 2;
        const uint32_t bW  = sb + ST_W * 2;

        #pragma unroll
        for (int ks = 0; ks < 2; ks++) {
            uint32_t fxh[4][4], fxl[4][4], fw[8][2];
            #pragma unroll
            for (int mt = 0; mt < 4; mt++) {
                uint32_t oa = (uint32_t)((a_row + mt * 16) * (SPAD * 2) + ks * 32 + a_kb);
                LDMX4(fxh[mt][0], fxh[mt][1], fxh[mt][2], fxh[mt][3], bXh + oa);
                LDMX4(fxl[mt][0], fxl[mt][1], fxl[mt][2], fxl[mt][3], bXl + oa);
            }
            #pragma unroll
            for (int p = 0; p < 4; p++) {
                uint32_t ob = (uint32_t)((b_row + p * 16) * (SPAD * 2) + ks * 32 + b_kb);
                LDMX4(fw[2 * p][0], fw[2 * p][1], fw[2 * p + 1][0], fw[2 * p + 1][1], bW + ob);
            }
            #pragma unroll
            for (int mt = 0; mt < 4; mt++)
                #pragma unroll
                for (int nt = 0; nt < 8; nt++) {
                    MMAF16(acc[mt][nt], fxh[mt], fw[nt]);
                    MMAF16(acc[mt][nt], fxl[mt], fw[nt]);
                }
        }

        st = st + 1; if (st >= NSTAGE) st -= NSTAGE;
    }

    // epilogue: bias + ReLU, fragment stores to g_h (sorted layout)
    #pragma unroll
    for (int nt = 0; nt < 8; nt++) {
        const int ncol = n0 + wn + nt * 8 + (lane & 3) * 2;
        const float bia0 = b1[e * HID + ncol];
        const float bia1 = b1[e * HID + ncol + 1];
        #pragma unroll
        for (int mt = 0; mt < 4; mt++) {
            int r0 = wm + mt * 16 + (lane >> 2);
            int ma = m0 + r0;
            if (ma < cnt) {
                float2 v;
                v.x = fmaxf(acc[mt][nt][0] + bia0, 0.f);
                v.y = fmaxf(acc[mt][nt][1] + bia1, 0.f);
                *(float2*)(g_h + (size_t)(seg_lo + ma) * HID + ncol) = v;
            }
            int mb = ma + 8;
            if (mb < cnt) {
                float2 v;
                v.x = fmaxf(acc[mt][nt][2] + bia0, 0.f);
                v.y = fmaxf(acc[mt][nt][3] + bia1, 0.f);
                *(float2*)(g_h + (size_t)(seg_lo + mb) * HID + ncol) = v;
            }
        }
    }
}

// -------- kernel 4: out[tok] = h_sorted[s] @ W2[e] + b2[e], one warp per token --------
__global__ __launch_bounds__(256) void k_gemm2(
    const float* __restrict__ W2,
    const float* __restrict__ b2,
    float* __restrict__ out)
{
    int gwarp = (blockIdx.x * blockDim.x + threadIdx.x) >> 5;
    int lane  = threadIdx.x & 31;
    if (gwarp >= NTOK) return;
    int s   = gwarp;
    int e   = g_sorted_expert[s];
    int tok = g_sorted_idx[s];
    const float* hrow = g_h + (size_t)s * HID;
    const float* w2   = W2 + (size_t)e * HID * COUT;

    float a0 = 0.f, a1 = 0.f;
    #pragma unroll 4
    for (int i = lane; i < HID; i += 32) {
        float hv = hrow[i];
        float2 w = *(const float2*)(w2 + i * 2);
        a0 = fmaf(hv, w.x, a0);
        a1 = fmaf(hv, w.y, a1);
    }
    #pragma unroll
    for (int o = 16; o > 0; o >>= 1) {
        a0 += __shfl_xor_sync(0xFFFFFFFFu, a0, o);
        a1 += __shfl_xor_sync(0xFFFFFFFFu, a1, o);
    }
    if (lane == 0) {
        out[tok * 2 + 0] = a0 + b2[e * 2 + 0];
        out[tok * 2 + 1] = a1 + b2[e * 2 + 1];
    }
}

extern "C" void kernel_launch(void* const* d_in, const int* in_sizes, int n_in,
                              void* d_out, int out_size) {
    const float* X   = (const float*)d_in[0];      // [N, D]
    const void*  cid = d_in[1];                    // [N] int32 or int64
    const float* W1  = (const float*)d_in[2];      // [E, D, H]
    const float* b1  = (const float*)d_in[3];      // [E, H]
    const float* W2  = (const float*)d_in[4];      // [E, H, C]
    const float* b2  = (const float*)d_in[5];      // [E, C]
    float*       out = (float*)d_out;              // [N, C]

    cudaFuncSetAttribute(k_gemm1, cudaFuncAttributeMaxDynamicSharedMemorySize, SMEM_TOTAL);

    k_prep<<<1, 1024>>>((const int*)cid);
    k_split_x<<<(int)(((size_t)NTOK * DIM / 4 + 255) / 256), 256>>>(X);
    k_split_w1<<<dim3(HID / 32, DIM / 32, NEXP), dim3(32, 8)>>>(W1);

    dim3 grid1(HID / BN, NTOK / BM, NEXP);
    k_gemm1<<<grid1, 256, SMEM_TOTAL>>>(b1);

    k_gemm2<<<(NTOK * 32 + 255) / 256, 256>>>(W2, b2, out);
}

// round 10
// speedup vs baseline: 2.6517x; 1.0055x over previous
#include <cuda_runtime.h>
#include <cuda_fp16.h>
#include <cuda_bf16.h>
#include <cstdint>

// Problem constants
#define NTOK 16384
#define DIM  768
#define HID  768
#define COUT 2
#define NEXP 20

// GEMM1 tiling (HMMA warp-level, cp.async 3-stage pipeline, 512 threads)
#define BM 128
#define BN 256
#define BK 32                  // fp16 K elems per stage
#define NITER (DIM / BK)       // 24
#define SPAD 40                // padded smem row stride in fp16 (80B)
#define NSTAGE 3
#define ST_XL (BM * SPAD)                  // halfs
#define ST_W  (2 * BM * SPAD)
#define STAGE_HALFS (2 * BM * SPAD + BN * SPAD)   // 20480
#define STAGE_BYTES (STAGE_HALFS * 2)             // 40960
#define SMEM_TOTAL (NSTAGE * STAGE_BYTES)         // 122880

// ---------------- device scratch ----------------
__device__ int    g_offsets[NEXP + 1];
__device__ int    g_sorted_idx[NTOK];
__device__ int    g_sorted_expert[NTOK];
__device__ float  g_h[(size_t)NTOK * HID];                 // 50 MB
__device__ __half g_xh[(size_t)NTOK * DIM];                // hi split of X (fp16)
__device__ __half g_xl[(size_t)NTOK * DIM];                // lo split of X (fp16)
__device__ __half g_w1f[(size_t)NEXP * HID * DIM];         // W1^T fp16, [e][n][k]

__device__ __forceinline__ uint32_t smem_u32(const void* p) {
    uint32_t a;
    asm("{ .reg .u64 t; cvta.to.shared.u64 t, %1; cvt.u32.u64 %0, t; }" : "=r"(a) : "l"(p));
    return a;
}

#define CP16(dst, src) \
    asm volatile("cp.async.cg.shared.global [%0], [%1], 16;" :: "r"(dst), "l"(src))
#define CP_COMMIT() asm volatile("cp.async.commit_group;")

#define LDMX4(r0, r1, r2, r3, a) \
    asm volatile("ldmatrix.sync.aligned.m8n8.x4.shared.b16 {%0,%1,%2,%3}, [%4];" \
        : "=r"(r0), "=r"(r1), "=r"(r2), "=r"(r3) : "r"(a))

#define MMAF16(d, a, b) \
    asm volatile("mma.sync.aligned.m16n8k16.row.col.f32.f16.f16.f32 " \
        "{%0,%1,%2,%3}, {%4,%5,%6,%7}, {%8,%9}, {%0,%1,%2,%3};" \
        : "+f"((d)[0]), "+f"((d)[1]), "+f"((d)[2]), "+f"((d)[3]) \
        : "r"((a)[0]), "r"((a)[1]), "r"((a)[2]), "r"((a)[3]), "r"((b)[0]), "r"((b)[1]))

// -------- kernel 1: fused prologue (detect + hist + scan + scatter) --------
__global__ __launch_bounds__(1024) void k_prep(const int* __restrict__ idx32) {
    __shared__ int s_cnt[NEXP];
    __shared__ int s_off[NEXP + 1];
    __shared__ int s_is64;
    const int t = threadIdx.x, lane = t & 31;

    if (t < NEXP) s_cnt[t] = 0;
    if (t == 0) s_is64 = 1;
    __syncthreads();

    for (int i = t; i < NTOK; i += 1024)
        if ((i & 1) && idx32[i] != 0) s_is64 = 0;
    __syncthreads();
    const int is64 = s_is64;

    for (int n = t; n < NTOK; n += 1024) {
        int e = is64 ? (int)((const long long*)idx32)[n] : idx32[n];
        unsigned m = __match_any_sync(0xFFFFFFFFu, e);
        if (lane == (__ffs(m) - 1)) atomicAdd(&s_cnt[e], __popc(m));
    }
    __syncthreads();

    if (t == 0) {
        int off = 0;
        for (int e = 0; e < NEXP; e++) { s_off[e] = off; off += s_cnt[e]; }
        s_off[NEXP] = off;
    }
    __syncthreads();
    if (t <= NEXP) g_offsets[t] = s_off[t];
    if (t < NEXP)  s_cnt[t] = s_off[t];
    __syncthreads();

    for (int n = t; n < NTOK; n += 1024) {
        int e = is64 ? (int)((const long long*)idx32)[n] : idx32[n];
        unsigned m = __match_any_sync(0xFFFFFFFFu, e);
        int leader = __ffs(m) - 1;
        int rank = __popc(m & ((1u << lane) - 1));
        int base = 0;
        if (lane == leader) base = atomicAdd(&s_cnt[e], __popc(m));
        base = __shfl_sync(0xFFFFFFFFu, base, leader);
        int p = base + rank;
        g_sorted_idx[p] = n;
        g_sorted_expert[p] = e;
    }
}

// -------- kernel 2a: split X into fp16 hi/lo --------
__global__ __launch_bounds__(256) void k_split_x(const float* __restrict__ X) {
    size_t i = ((size_t)blockIdx.x * 256 + threadIdx.x) * 4;
    if (i >= (size_t)NTOK * DIM) return;
    float4 v = *(const float4*)(X + i);
    float f[4] = {v.x, v.y, v.z, v.w};
    unsigned short h[4], l[4];
    #pragma unroll
    for (int j = 0; j < 4; j++) {
        __half hh = __float2half_rn(f[j]);
        __half hl = __float2half_rn(f[j] - __half2float(hh));
        h[j] = __half_as_ushort(hh);
        l[j] = __half_as_ushort(hl);
    }
    *(uint2*)(g_xh + i) = make_uint2((unsigned)h[0] | ((unsigned)h[1] << 16),
                                     (unsigned)h[2] | ((unsigned)h[3] << 16));
    *(uint2*)(g_xl + i) = make_uint2((unsigned)l[0] | ((unsigned)l[1] << 16),
                                     (unsigned)l[2] | ((unsigned)l[3] << 16));
}

// -------- kernel 2b: transpose W1 -> [e][n][k] fp16 --------
__global__ __launch_bounds__(256) void k_split_w1(const float* __restrict__ W1) {
    __shared__ float tile[32][33];
    const int e = blockIdx.z;
    const int kt = blockIdx.y * 32;
    const int nt = blockIdx.x * 32;
    const float* src = W1 + (size_t)e * DIM * HID;

    for (int i = threadIdx.y; i < 32; i += 8)
        tile[i][threadIdx.x] = src[(size_t)(kt + i) * HID + nt + threadIdx.x];
    __syncthreads();

    for (int i = threadIdx.y; i < 32; i += 8) {
        float v = tile[threadIdx.x][i];
        size_t o = ((size_t)e * HID + nt + i) * DIM + kt + threadIdx.x;
        g_w1f[o] = __float2half_rn(v);
    }
}

// -------- kernel 3: grouped GEMM1, fp16 HMMA + cp.async pipeline, 16 warps --------
// h_sorted[s,:] = relu( X[tok(s),:] @ W1[e] + b1[e] ),  D = Xh*W + Xl*W in fp32.
// grid = (HID/BN=3, NTOK/BM, NEXP), 512 thr = 16 warps (4 M x 4 N), warp tile 32x64.
__global__ __launch_bounds__(512, 1) void k_gemm1(const float* __restrict__ b1)
{
    extern __shared__ __align__(16) __half dynsm[];
    const uint32_t smem0 = smem_u32(dynsm);

    const int e = blockIdx.z;
    const int seg_lo = g_offsets[e];
    const int cnt    = g_offsets[e + 1] - seg_lo;
    const int m0 = blockIdx.y * BM;
    if (m0 >= cnt) return;
    const int n0 = blockIdx.x * BN;
    const int tid  = threadIdx.x;
    const int wid  = tid >> 5;
    const int lane = tid & 31;

    const int wm = (wid >> 2) * 32;   // warp M offset (0,32,64,96)
    const int wn = (wid & 3) * 64;    // warp N offset (0,64,128,192)

    // global->smem cp.async mapping: 4 x 16B per thread
    //  X: thread (r = tid&127, q = tid>>7 in 0..3) loads Xh[r, q*8] and Xl[r, q*8]
    //  W: thread (wr = tid&255, wq = tid>>8 in 0..1) loads W[wr, wq*16] and W[wr, wq*16+8]
    const int r_ld = tid & 127;
    const int q_ld = tid >> 7;                  // 0..3
    const int m_ld = m0 + r_ld;
    const int tok  = (m_ld < cnt) ? g_sorted_idx[seg_lo + m_ld] : g_sorted_idx[seg_lo];
    const __half* pXh = g_xh + (size_t)tok * DIM + q_ld * 8;
    const __half* pXl = g_xl + (size_t)tok * DIM + q_ld * 8;
    const int wr = tid & 255;
    const int wq = tid >> 8;                    // 0..1
    const __half* pW = g_w1f + ((size_t)e * HID + n0 + wr) * DIM + wq * 16;
    const uint32_t dX_off = (uint32_t)(r_ld * SPAD + q_ld * 8) * 2;   // bytes
    const uint32_t dW_off = (uint32_t)(wr * SPAD + wq * 16) * 2;

    // ldmatrix lane addressing (byte offsets within a stage; row stride 80B)
    const int a_row = wm + (lane & 15);
    const int a_kb  = (lane >> 4) * 16;
    const int b_row = wn + ((lane >> 4) & 1) * 8 + (lane & 7);
    const int b_kb  = ((lane >> 3) & 1) * 16;

    float acc[2][8][4];
    #pragma unroll
    for (int i = 0; i < 2; i++)
        #pragma unroll
        for (int j = 0; j < 8; j++)
            #pragma unroll
            for (int q = 0; q < 4; q++) acc[i][j][q] = 0.f;

    auto issue = [&](int c, int st) {
        const int kg = c * BK;
        const uint32_t sb = smem0 + st * STAGE_BYTES;
        CP16(sb + dX_off,              pXh + kg);
        CP16(sb + ST_XL * 2 + dX_off,  pXl + kg);
        CP16(sb + ST_W * 2 + dW_off,       pW + kg);
        CP16(sb + ST_W * 2 + dW_off + 16,  pW + kg + 8);
        CP_COMMIT();
    };

    issue(0, 0);
    issue(1, 1);

    int st = 0;
    for (int c = 0; c < NITER; c++) {
        if (c + 1 < NITER) { asm volatile("cp.async.wait_group 1;" ::: "memory"); }
        else               { asm volatile("cp.async.wait_group 0;" ::: "memory"); }
        __syncthreads();

        if (c + 2 < NITER) {
            int st2 = st + 2; if (st2 >= NSTAGE) st2 -= NSTAGE;
            issue(c + 2, st2);
        }

        const uint32_t sb  = smem0 + st * STAGE_BYTES;
        const uint32_t bXh = sb;
        const uint32_t bXl = sb + ST_XL * 2;
        const uint32_t bW  = sb + ST_W * 2;

        #pragma unroll
        for (int ks = 0; ks < 2; ks++) {
            uint32_t fxh[2][4], fxl[2][4], fw[8][2];
            #pragma unroll
            for (int mt = 0; mt < 2; mt++) {
                uint32_t oa = (uint32_t)((a_row + mt * 16) * (SPAD * 2) + ks * 32 + a_kb);
                LDMX4(fxh[mt][0], fxh[mt][1], fxh[mt][2], fxh[mt][3], bXh + oa);
                LDMX4(fxl[mt][0], fxl[mt][1], fxl[mt][2], fxl[mt][3], bXl + oa);
            }
            #pragma unroll
            for (int p = 0; p < 4; p++) {
                uint32_t ob = (uint32_t)((b_row + p * 16) * (SPAD * 2) + ks * 32 + b_kb);
                LDMX4(fw[2 * p][0], fw[2 * p][1], fw[2 * p + 1][0], fw[2 * p + 1][1], bW + ob);
            }
            #pragma unroll
            for (int mt = 0; mt < 2; mt++)
                #pragma unroll
                for (int nt = 0; nt < 8; nt++) {
                    MMAF16(acc[mt][nt], fxh[mt], fw[nt]);
                    MMAF16(acc[mt][nt], fxl[mt], fw[nt]);
                }
        }

        st = st + 1; if (st >= NSTAGE) st -= NSTAGE;
    }

    // epilogue: bias + ReLU, fragment stores to g_h (sorted layout)
    #pragma unroll
    for (int nt = 0; nt < 8; nt++) {
        const int ncol = n0 + wn + nt * 8 + (lane & 3) * 2;
        const float bia0 = b1[e * HID + ncol];
        const float bia1 = b1[e * HID + ncol + 1];
        #pragma unroll
        for (int mt = 0; mt < 2; mt++) {
            int r0 = wm + mt * 16 + (lane >> 2);
            int ma = m0 + r0;
            if (ma < cnt) {
                float2 v;
                v.x = fmaxf(acc[mt][nt][0] + bia0, 0.f);
                v.y = fmaxf(acc[mt][nt][1] + bia1, 0.f);
                *(float2*)(g_h + (size_t)(seg_lo + ma) * HID + ncol) = v;
            }
            int mb = ma + 8;
            if (mb < cnt) {
                float2 v;
                v.x = fmaxf(acc[mt][nt][2] + bia0, 0.f);
                v.y = fmaxf(acc[mt][nt][3] + bia1, 0.f);
                *(float2*)(g_h + (size_t)(seg_lo + mb) * HID + ncol) = v;
            }
        }
    }
}

// -------- kernel 4: out[tok] = h_sorted[s] @ W2[e] + b2[e], one warp per token --------
__global__ __launch_bounds__(256) void k_gemm2(
    const float* __restrict__ W2,
    const float* __restrict__ b2,
    float* __restrict__ out)
{
    int gwarp = (blockIdx.x * blockDim.x + threadIdx.x) >> 5;
    int lane  = threadIdx.x & 31;
    if (gwarp >= NTOK) return;
    int s   = gwarp;
    int e   = g_sorted_expert[s];
    int tok = g_sorted_idx[s];
    const float* hrow = g_h + (size_t)s * HID;
    const float* w2   = W2 + (size_t)e * HID * COUT;

    float a0 = 0.f, a1 = 0.f;
    #pragma unroll 4
    for (int i = lane; i < HID; i += 32) {
        float hv = hrow[i];
        float2 w = *(const float2*)(w2 + i * 2);
        a0 = fmaf(hv, w.x, a0);
        a1 = fmaf(hv, w.y, a1);
    }
    #pragma unroll
    for (int o = 16; o > 0; o >>= 1) {
        a0 += __shfl_xor_sync(0xFFFFFFFFu, a0, o);
        a1 += __shfl_xor_sync(0xFFFFFFFFu, a1, o);
    }
    if (lane == 0) {
        out[tok * 2 + 0] = a0 + b2[e * 2 + 0];
        out[tok * 2 + 1] = a1 + b2[e * 2 + 1];
    }
}

extern "C" void kernel_launch(void* const* d_in, const int* in_sizes, int n_in,
                              void* d_out, int out_size) {
    const float* X   = (const float*)d_in[0];      // [N, D]
    const void*  cid = d_in[1];                    // [N] int32 or int64
    const float* W1  = (const float*)d_in[2];      // [E, D, H]
    const float* b1  = (const float*)d_in[3];      // [E, H]
    const float* W2  = (const float*)d_in[4];      // [E, H, C]
    const float* b2  = (const float*)d_in[5];      // [E, C]
    float*       out = (float*)d_out;              // [N, C]

    cudaFuncSetAttribute(k_gemm1, cudaFuncAttributeMaxDynamicSharedMemorySize, SMEM_TOTAL);

    k_prep<<<1, 1024>>>((const int*)cid);
    k_split_x<<<(int)(((size_t)NTOK * DIM / 4 + 255) / 256), 256>>>(X);
    k_split_w1<<<dim3(HID / 32, DIM / 32, NEXP), dim3(32, 8)>>>(W1);

    dim3 grid1(HID / BN, NTOK / BM, NEXP);
    k_gemm1<<<grid1, 512, SMEM_TOTAL>>>(b1);

    k_gemm2<<<(NTOK * 32 + 255) / 256, 256>>>(W2, b2, out);
}

// round 11
// speedup vs baseline: 3.5300x; 1.3312x over previous
#include <cuda_runtime.h>
#include <cuda_fp16.h>
#include <cuda_bf16.h>
#include <cstdint>

// Problem constants
#define NTOK 16384
#define DIM  768
#define HID  768
#define COUT 2
#define NEXP 20

// GEMM1 tiling (fp16 HMMA single-pass, cp.async 4-stage pipeline, 512 threads)
#define BM 128
#define BN 256
#define BK 32                  // fp16 K elems per stage
#define NITER (DIM / BK)       // 24
#define SPAD 40                // padded smem row stride in fp16 (80B)
#define NSTAGE 4
#define ST_W  (BM * SPAD)                         // halfs offset of W tile
#define STAGE_HALFS (BM * SPAD + BN * SPAD)       // 15360
#define STAGE_BYTES (STAGE_HALFS * 2)             // 30720
#define SMEM_TOTAL (NSTAGE * STAGE_BYTES)         // 122880

// ---------------- device scratch ----------------
__device__ int    g_offsets[NEXP + 1];
__device__ int    g_sorted_idx[NTOK];
__device__ int    g_sorted_expert[NTOK];
__device__ float  g_h[(size_t)NTOK * HID];                 // 50 MB
__device__ __half g_xf[(size_t)NTOK * DIM];                // X in fp16
__device__ __half g_w1f[(size_t)NEXP * HID * DIM];         // W1^T fp16, [e][n][k]

__device__ __forceinline__ uint32_t smem_u32(const void* p) {
    uint32_t a;
    asm("{ .reg .u64 t; cvta.to.shared.u64 t, %1; cvt.u32.u64 %0, t; }" : "=r"(a) : "l"(p));
    return a;
}

#define CP16(dst, src) \
    asm volatile("cp.async.cg.shared.global [%0], [%1], 16;" :: "r"(dst), "l"(src))
#define CP_COMMIT() asm volatile("cp.async.commit_group;")

#define LDMX4(r0, r1, r2, r3, a) \
    asm volatile("ldmatrix.sync.aligned.m8n8.x4.shared.b16 {%0,%1,%2,%3}, [%4];" \
        : "=r"(r0), "=r"(r1), "=r"(r2), "=r"(r3) : "r"(a))

#define MMAF16(d, a, b) \
    asm volatile("mma.sync.aligned.m16n8k16.row.col.f32.f16.f16.f32 " \
        "{%0,%1,%2,%3}, {%4,%5,%6,%7}, {%8,%9}, {%0,%1,%2,%3};" \
        : "+f"((d)[0]), "+f"((d)[1]), "+f"((d)[2]), "+f"((d)[3]) \
        : "r"((a)[0]), "r"((a)[1]), "r"((a)[2]), "r"((a)[3]), "r"((b)[0]), "r"((b)[1]))

// -------- kernel 1: fused prologue (detect + hist + scan + scatter) --------
__global__ __launch_bounds__(1024) void k_prep(const int* __restrict__ idx32) {
    __shared__ int s_cnt[NEXP];
    __shared__ int s_off[NEXP + 1];
    __shared__ int s_is64;
    const int t = threadIdx.x, lane = t & 31;

    if (t < NEXP) s_cnt[t] = 0;
    if (t == 0) s_is64 = 1;
    __syncthreads();

    for (int i = t; i < NTOK; i += 1024)
        if ((i & 1) && idx32[i] != 0) s_is64 = 0;
    __syncthreads();
    const int is64 = s_is64;

    for (int n = t; n < NTOK; n += 1024) {
        int e = is64 ? (int)((const long long*)idx32)[n] : idx32[n];
        unsigned m = __match_any_sync(0xFFFFFFFFu, e);
        if (lane == (__ffs(m) - 1)) atomicAdd(&s_cnt[e], __popc(m));
    }
    __syncthreads();

    if (t == 0) {
        int off = 0;
        for (int e = 0; e < NEXP; e++) { s_off[e] = off; off += s_cnt[e]; }
        s_off[NEXP] = off;
    }
    __syncthreads();
    if (t <= NEXP) g_offsets[t] = s_off[t];
    if (t < NEXP)  s_cnt[t] = s_off[t];
    __syncthreads();

    for (int n = t; n < NTOK; n += 1024) {
        int e = is64 ? (int)((const long long*)idx32)[n] : idx32[n];
        unsigned m = __match_any_sync(0xFFFFFFFFu, e);
        int leader = __ffs(m) - 1;
        int rank = __popc(m & ((1u << lane) - 1));
        int base = 0;
        if (lane == leader) base = atomicAdd(&s_cnt[e], __popc(m));
        base = __shfl_sync(0xFFFFFFFFu, base, leader);
        int p = base + rank;
        g_sorted_idx[p] = n;
        g_sorted_expert[p] = e;
    }
}

// -------- kernel 2a: convert X to fp16 --------
__global__ __launch_bounds__(256) void k_convert_x(const float* __restrict__ X) {
    size_t i = ((size_t)blockIdx.x * 256 + threadIdx.x) * 4;
    if (i >= (size_t)NTOK * DIM) return;
    float4 v = *(const float4*)(X + i);
    unsigned short h[4];
    h[0] = __half_as_ushort(__float2half_rn(v.x));
    h[1] = __half_as_ushort(__float2half_rn(v.y));
    h[2] = __half_as_ushort(__float2half_rn(v.z));
    h[3] = __half_as_ushort(__float2half_rn(v.w));
    *(uint2*)(g_xf + i) = make_uint2((unsigned)h[0] | ((unsigned)h[1] << 16),
                                     (unsigned)h[2] | ((unsigned)h[3] << 16));
}

// -------- kernel 2b: transpose W1 -> [e][n][k] fp16 --------
__global__ __launch_bounds__(256) void k_split_w1(const float* __restrict__ W1) {
    __shared__ float tile[32][33];
    const int e = blockIdx.z;
    const int kt = blockIdx.y * 32;
    const int nt = blockIdx.x * 32;
    const float* src = W1 + (size_t)e * DIM * HID;

    for (int i = threadIdx.y; i < 32; i += 8)
        tile[i][threadIdx.x] = src[(size_t)(kt + i) * HID + nt + threadIdx.x];
    __syncthreads();

    for (int i = threadIdx.y; i < 32; i += 8) {
        float v = tile[threadIdx.x][i];
        size_t o = ((size_t)e * HID + nt + i) * DIM + kt + threadIdx.x;
        g_w1f[o] = __float2half_rn(v);
    }
}

// -------- kernel 3: grouped GEMM1, single-pass fp16 HMMA + 4-stage cp.async --------
// h_sorted[s,:] = relu( X16[tok(s),:] @ W16[e] + b1[e] ), fp32 accum.
// grid = (HID/BN=3, NTOK/BM, NEXP), 512 thr = 16 warps (4 M x 4 N), warp tile 32x64.
__global__ __launch_bounds__(512, 1) void k_gemm1(const float* __restrict__ b1)
{
    extern __shared__ __align__(16) __half dynsm[];
    const uint32_t smem0 = smem_u32(dynsm);

    const int e = blockIdx.z;
    const int seg_lo = g_offsets[e];
    const int cnt    = g_offsets[e + 1] - seg_lo;
    const int m0 = blockIdx.y * BM;
    if (m0 >= cnt) return;
    const int n0 = blockIdx.x * BN;
    const int tid  = threadIdx.x;
    const int wid  = tid >> 5;
    const int lane = tid & 31;

    const int wm = (wid >> 2) * 32;   // warp M offset (0,32,64,96)
    const int wn = (wid & 3) * 64;    // warp N offset (0,64,128,192)

    // global->smem cp.async mapping: 3 x 16B per thread
    //  X: thread (r = tid>>2 in 0..127, q = tid&3) loads X[r, q*8]
    //  W: thread (wr = tid&255, wq = tid>>8 in 0..1) loads W[wr, wq*16], W[wr, wq*16+8]
    const int r_ld = tid >> 2;
    const int q_ld = tid & 3;
    const int m_ld = m0 + r_ld;
    const int tok  = (m_ld < cnt) ? g_sorted_idx[seg_lo + m_ld] : g_sorted_idx[seg_lo];
    const __half* pX = g_xf + (size_t)tok * DIM + q_ld * 8;
    const int wr = tid & 255;
    const int wq = tid >> 8;
    const __half* pW = g_w1f + ((size_t)e * HID + n0 + wr) * DIM + wq * 16;
    const uint32_t dX_off = (uint32_t)(r_ld * SPAD + q_ld * 8) * 2;   // bytes
    const uint32_t dW_off = (uint32_t)(wr * SPAD + wq * 16) * 2;

    // ldmatrix lane addressing (byte offsets within a stage; row stride 80B)
    const int a_row = wm + (lane & 15);
    const int a_kb  = (lane >> 4) * 16;
    const int b_row = wn + ((lane >> 4) & 1) * 8 + (lane & 7);
    const int b_kb  = ((lane >> 3) & 1) * 16;

    float acc[2][8][4];
    #pragma unroll
    for (int i = 0; i < 2; i++)
        #pragma unroll
        for (int j = 0; j < 8; j++)
            #pragma unroll
            for (int q = 0; q < 4; q++) acc[i][j][q] = 0.f;

    auto issue = [&](int c, int st) {
        const int kg = c * BK;
        const uint32_t sb = smem0 + st * STAGE_BYTES;
        CP16(sb + dX_off,                 pX + kg);
        CP16(sb + ST_W * 2 + dW_off,      pW + kg);
        CP16(sb + ST_W * 2 + dW_off + 16, pW + kg + 8);
        CP_COMMIT();
    };

    issue(0, 0);
    issue(1, 1);
    issue(2, 2);

    int st = 0;
    for (int c = 0; c < NITER; c++) {
        // group for stage c must be complete; allowed pending newer groups:
        if (c + 3 <= NITER - 1)      { asm volatile("cp.async.wait_group 2;" ::: "memory"); }
        else if (c + 2 <= NITER - 1) { asm volatile("cp.async.wait_group 1;" ::: "memory"); }
        else                         { asm volatile("cp.async.wait_group 0;" ::: "memory"); }
        __syncthreads();

        if (c + 3 < NITER) {
            int st3 = st + 3; if (st3 >= NSTAGE) st3 -= NSTAGE;
            issue(c + 3, st3);
        }

        const uint32_t sb = smem0 + st * STAGE_BYTES;
        const uint32_t bX = sb;
        const uint32_t bW = sb + ST_W * 2;

        #pragma unroll
        for (int ks = 0; ks < 2; ks++) {
            uint32_t fx[2][4], fw[8][2];
            #pragma unroll
            for (int mt = 0; mt < 2; mt++) {
                uint32_t oa = (uint32_t)((a_row + mt * 16) * (SPAD * 2) + ks * 32 + a_kb);
                LDMX4(fx[mt][0], fx[mt][1], fx[mt][2], fx[mt][3], bX + oa);
            }
            #pragma unroll
            for (int p = 0; p < 4; p++) {
                uint32_t ob = (uint32_t)((b_row + p * 16) * (SPAD * 2) + ks * 32 + b_kb);
                LDMX4(fw[2 * p][0], fw[2 * p][1], fw[2 * p + 1][0], fw[2 * p + 1][1], bW + ob);
            }
            #pragma unroll
            for (int mt = 0; mt < 2; mt++)
                #pragma unroll
                for (int nt = 0; nt < 8; nt++)
                    MMAF16(acc[mt][nt], fx[mt], fw[nt]);
        }

        st = st + 1; if (st >= NSTAGE) st -= NSTAGE;
    }

    // epilogue: bias + ReLU, fragment stores to g_h (sorted layout)
    #pragma unroll
    for (int nt = 0; nt < 8; nt++) {
        const int ncol = n0 + wn + nt * 8 + (lane & 3) * 2;
        const float bia0 = b1[e * HID + ncol];
        const float bia1 = b1[e * HID + ncol + 1];
        #pragma unroll
        for (int mt = 0; mt < 2; mt++) {
            int r0 = wm + mt * 16 + (lane >> 2);
            int ma = m0 + r0;
            if (ma < cnt) {
                float2 v;
                v.x = fmaxf(acc[mt][nt][0] + bia0, 0.f);
                v.y = fmaxf(acc[mt][nt][1] + bia1, 0.f);
                *(float2*)(g_h + (size_t)(seg_lo + ma) * HID + ncol) = v;
            }
            int mb = ma + 8;
            if (mb < cnt) {
                float2 v;
                v.x = fmaxf(acc[mt][nt][2] + bia0, 0.f);
                v.y = fmaxf(acc[mt][nt][3] + bia1, 0.f);
                *(float2*)(g_h + (size_t)(seg_lo + mb) * HID + ncol) = v;
            }
        }
    }
}

// -------- kernel 4: out[tok] = h_sorted[s] @ W2[e] + b2[e], one warp per token --------
__global__ __launch_bounds__(256) void k_gemm2(
    const float* __restrict__ W2,
    const float* __restrict__ b2,
    float* __restrict__ out)
{
    int gwarp = (blockIdx.x * blockDim.x + threadIdx.x) >> 5;
    int lane  = threadIdx.x & 31;
    if (gwarp >= NTOK) return;
    int s   = gwarp;
    int e   = g_sorted_expert[s];
    int tok = g_sorted_idx[s];
    const float* hrow = g_h + (size_t)s * HID;
    const float* w2   = W2 + (size_t)e * HID * COUT;

    float a0 = 0.f, a1 = 0.f;
    #pragma unroll 4
    for (int i = lane; i < HID; i += 32) {
        float hv = hrow[i];
        float2 w = *(const float2*)(w2 + i * 2);
        a0 = fmaf(hv, w.x, a0);
        a1 = fmaf(hv, w.y, a1);
    }
    #pragma unroll
    for (int o = 16; o > 0; o >>= 1) {
        a0 += __shfl_xor_sync(0xFFFFFFFFu, a0, o);
        a1 += __shfl_xor_sync(0xFFFFFFFFu, a1, o);
    }
    if (lane == 0) {
        out[tok * 2 + 0] = a0 + b2[e * 2 + 0];
        out[tok * 2 + 1] = a1 + b2[e * 2 + 1];
    }
}

extern "C" void kernel_launch(void* const* d_in, const int* in_sizes, int n_in,
                              void* d_out, int out_size) {
    const float* X   = (const float*)d_in[0];      // [N, D]
    const void*  cid = d_in[1];                    // [N] int32 or int64
    const float* W1  = (const float*)d_in[2];      // [E, D, H]
    const float* b1  = (const float*)d_in[3];      // [E, H]
    const float* W2  = (const float*)d_in[4];      // [E, H, C]
    const float* b2  = (const float*)d_in[5];      // [E, C]
    float*       out = (float*)d_out;              // [N, C]

    cudaFuncSetAttribute(k_gemm1, cudaFuncAttributeMaxDynamicSharedMemorySize, SMEM_TOTAL);

    k_prep<<<1, 1024>>>((const int*)cid);
    k_convert_x<<<(int)(((size_t)NTOK * DIM / 4 + 255) / 256), 256>>>(X);
    k_split_w1<<<dim3(HID / 32, DIM / 32, NEXP), dim3(32, 8)>>>(W1);

    dim3 grid1(HID / BN, NTOK / BM, NEXP);
    k_gemm1<<<grid1, 512, SMEM_TOTAL>>>(b1);

    k_gemm2<<<(NTOK * 32 + 255) / 256, 256>>>(W2, b2, out);
}